// round 4
// baseline (speedup 1.0000x reference)
#include <cuda_runtime.h>
#include <math.h>
#include <stdint.h>

#define N_NODES 50000
#define N_EDGES 600000
#define NF      128
#define NG      512
#define NC      10
#define BN_EPS  1e-5f

// ---------------- scratch (device globals) ---------------------------------
__device__ int      g_deg   [N_NODES];
__device__ int      g_rowptr[N_NODES + 1];
__device__ int      g_cursor[N_NODES];
__device__ int      g_csrc  [N_EDGES];          // CSR: src ids grouped by dst
__device__ float    g_dinv  [N_NODES];
__device__ float    g_y     [N_NODES * NF];
__device__ float    g_h     [N_NODES * NF];
__device__ unsigned g_gmax  [NG * NF];
__device__ float    g_g     [NG * NF];
__device__ float    g_m1    [NG * NF];
__device__ float    g_m2    [NG * 64];

// ---------------- helpers --------------------------------------------------
__device__ __forceinline__ unsigned enc_f(float v) {
    unsigned u = __float_as_uint(v);
    return (u & 0x80000000u) ? ~u : (u | 0x80000000u);
}
__device__ __forceinline__ float dec_f(unsigned u) {
    return (u & 0x80000000u) ? __uint_as_float(u & 0x7FFFFFFFu)
                             : __uint_as_float(~u);
}

// ---------------- CSR build -------------------------------------------------
__global__ void zero_i(int* p, int n) {
    int i = blockIdx.x * blockDim.x + threadIdx.x;
    if (i < n) p[i] = 0;
}
__global__ void zero_u(unsigned* p, int n) {
    int i = blockIdx.x * blockDim.x + threadIdx.x;
    if (i < n) p[i] = 0u;
}
__global__ void deg_count(const int* __restrict__ dst) {
    int e = blockIdx.x * blockDim.x + threadIdx.x;
    if (e < N_EDGES) atomicAdd(&g_deg[dst[e]], 1);
}
__global__ __launch_bounds__(1024) void scan_deg() {
    __shared__ int sums[1024];
    const int CH = (N_NODES + 1023) / 1024;
    int t = threadIdx.x;
    int base = t * CH;
    int s = 0;
    for (int i = 0; i < CH; ++i) {
        int idx = base + i;
        if (idx < N_NODES) s += g_deg[idx];
    }
    sums[t] = s;
    __syncthreads();
    for (int off = 1; off < 1024; off <<= 1) {
        int v = 0;
        if (t >= off) v = sums[t - off];
        __syncthreads();
        if (t >= off) sums[t] += v;
        __syncthreads();
    }
    int run = (t == 0) ? 0 : sums[t - 1];
    for (int i = 0; i < CH; ++i) {
        int idx = base + i;
        if (idx < N_NODES) {
            g_rowptr[idx] = run;
            g_cursor[idx] = run;
            g_dinv[idx]   = rsqrtf((float)g_deg[idx] + 1.0f);
            run += g_deg[idx];
        }
    }
    if (t == 1023) g_rowptr[N_NODES] = run;
}
__global__ void csr_fill(const int* __restrict__ src, const int* __restrict__ dst) {
    int e = blockIdx.x * blockDim.x + threadIdx.x;
    if (e < N_EDGES) {
        int pos = atomicAdd(&g_cursor[dst[e]], 1);
        g_csrc[pos] = src[e];
    }
}

// ---------------- GEMM via packed fma.rn.f32x2 ------------------------------
// out[r,c] = sum_k A[r,k]*W[k,c]  (K = N = 128)
// 128x128 block tile, 256 threads, 8x8 per thread (as 8x4 f32x2 pairs), BK=8.
// A tile stored DUPLICATED in smem so (a,a) pairs come straight from LDS.128.
__global__ __launch_bounds__(256)
void gemm_f32x2(const float* __restrict__ A, const float* __restrict__ W,
                float* __restrict__ out,
                const float* __restrict__ dinv, const float* __restrict__ bias,
                int nrows, int do_relu)
{
    __shared__ float Xs[8][264];    // [k][2*row] duplicated, padded (row stride 1056B)
    __shared__ float Ws[8][132];    // [k][col], padded

    const int tid  = threadIdx.x;
    const int trow = tid >> 4;      // 0..15 -> rows trow*8..+7
    const int tcol = tid & 15;      // 0..15 -> cols tcol*8..+7
    const int row0 = blockIdx.x * 128;

    unsigned long long acc[8][4];   // [r][cpair]: (c=2cp, c=2cp+1)
    #pragma unroll
    for (int r = 0; r < 8; ++r)
        #pragma unroll
        for (int c = 0; c < 4; ++c) acc[r][c] = 0ull;

    const int lr = tid >> 1;        // 0..127 (A-loader row)
    const int lk = (tid & 1) * 4;   // 0 or 4 (A-loader k)
    const int wk = tid >> 5;        // 0..7   (W-loader k)
    const int wc = (tid & 31) * 4;  // W-loader col

    for (int k0 = 0; k0 < 128; k0 += 8) {
        float4 av = make_float4(0.f, 0.f, 0.f, 0.f);
        int gr = row0 + lr;
        if (gr < nrows)
            av = *reinterpret_cast<const float4*>(&A[gr * 128 + k0 + lk]);
        // duplicated transpose-store: Xs[k][2*lr] = Xs[k][2*lr+1] = a
        *reinterpret_cast<float2*>(&Xs[lk + 0][2 * lr]) = make_float2(av.x, av.x);
        *reinterpret_cast<float2*>(&Xs[lk + 1][2 * lr]) = make_float2(av.y, av.y);
        *reinterpret_cast<float2*>(&Xs[lk + 2][2 * lr]) = make_float2(av.z, av.z);
        *reinterpret_cast<float2*>(&Xs[lk + 3][2 * lr]) = make_float2(av.w, av.w);
        *reinterpret_cast<float4*>(&Ws[wk][wc]) =
            *reinterpret_cast<const float4*>(&W[(k0 + wk) * 128 + wc]);
        __syncthreads();

        #pragma unroll
        for (int kk = 0; kk < 8; ++kk) {
            // a-pairs: 16 duplicated floats = 4 LDS.128 = 8 (a,a) 64-bit pairs
            ulonglong2 a0 = *reinterpret_cast<ulonglong2*>(&Xs[kk][16 * trow +  0]);
            ulonglong2 a1 = *reinterpret_cast<ulonglong2*>(&Xs[kk][16 * trow +  4]);
            ulonglong2 a2 = *reinterpret_cast<ulonglong2*>(&Xs[kk][16 * trow +  8]);
            ulonglong2 a3 = *reinterpret_cast<ulonglong2*>(&Xs[kk][16 * trow + 12]);
            // b-pairs: 8 floats = 2 LDS.128 = 4 (b0,b1) pairs
            ulonglong2 b0 = *reinterpret_cast<ulonglong2*>(&Ws[kk][tcol * 8 + 0]);
            ulonglong2 b1 = *reinterpret_cast<ulonglong2*>(&Ws[kk][tcol * 8 + 4]);
            unsigned long long ap[8] = {a0.x, a0.y, a1.x, a1.y, a2.x, a2.y, a3.x, a3.y};
            unsigned long long bp[4] = {b0.x, b0.y, b1.x, b1.y};
            #pragma unroll
            for (int r = 0; r < 8; ++r)
                #pragma unroll
                for (int cp = 0; cp < 4; ++cp)
                    asm("fma.rn.f32x2 %0, %1, %2, %0;"
                        : "+l"(acc[r][cp]) : "l"(ap[r]), "l"(bp[cp]));
        }
        __syncthreads();
    }

    #pragma unroll
    for (int r = 0; r < 8; ++r) {
        int grow = row0 + trow * 8 + r;
        if (grow >= nrows) continue;
        float s = dinv ? dinv[grow] : 1.0f;
        float v[8];
        #pragma unroll
        for (int cp = 0; cp < 4; ++cp) {
            float lo, hi;
            asm("mov.b64 {%0, %1}, %2;" : "=f"(lo), "=f"(hi) : "l"(acc[r][cp]));
            v[cp * 2 + 0] = lo;
            v[cp * 2 + 1] = hi;
        }
        #pragma unroll
        for (int c4 = 0; c4 < 2; ++c4) {
            int cc = tcol * 8 + c4 * 4;
            float4 o;
            o.x = v[c4 * 4 + 0] * s;
            o.y = v[c4 * 4 + 1] * s;
            o.z = v[c4 * 4 + 2] * s;
            o.w = v[c4 * 4 + 3] * s;
            if (bias) {
                float4 bv = *reinterpret_cast<const float4*>(&bias[cc]);
                o.x += bv.x; o.y += bv.y; o.z += bv.z; o.w += bv.w;
            }
            if (do_relu) {
                o.x = fmaxf(o.x, 0.f); o.y = fmaxf(o.y, 0.f);
                o.z = fmaxf(o.z, 0.f); o.w = fmaxf(o.w, 0.f);
            }
            *reinterpret_cast<float4*>(&out[grow * 128 + cc]) = o;
        }
    }
}

// ---------------- aggregate (CSR gather) + fused epilogue ------------------
// MODE 0: h = relu(dinv*(sum + self) + bias)
// MODE 1: same, then BN(eval) + per-graph atomicMax (no h store)
template <int MODE>
__global__ __launch_bounds__(256)
void aggregate(const float* __restrict__ y, const float* __restrict__ bias,
               float* __restrict__ h,
               const int* __restrict__ batch,
               const float* __restrict__ gamma, const float* __restrict__ beta,
               const float* __restrict__ rmean, const float* __restrict__ rvar)
{
    int node = blockIdx.x * 8 + (threadIdx.x >> 5);
    int lane = threadIdx.x & 31;
    if (node >= N_NODES) return;

    int p0 = g_rowptr[node];
    int p1 = g_rowptr[node + 1];

    float4 a = make_float4(0.f, 0.f, 0.f, 0.f);
    int e = p0;
    for (; e + 4 <= p1; e += 4) {
        int s0 = g_csrc[e + 0];
        int s1 = g_csrc[e + 1];
        int s2 = g_csrc[e + 2];
        int s3 = g_csrc[e + 3];
        float4 v0 = *reinterpret_cast<const float4*>(&y[s0 * 128 + lane * 4]);
        float4 v1 = *reinterpret_cast<const float4*>(&y[s1 * 128 + lane * 4]);
        float4 v2 = *reinterpret_cast<const float4*>(&y[s2 * 128 + lane * 4]);
        float4 v3 = *reinterpret_cast<const float4*>(&y[s3 * 128 + lane * 4]);
        a.x += (v0.x + v1.x) + (v2.x + v3.x);
        a.y += (v0.y + v1.y) + (v2.y + v3.y);
        a.z += (v0.z + v1.z) + (v2.z + v3.z);
        a.w += (v0.w + v1.w) + (v2.w + v3.w);
    }
    for (; e < p1; ++e) {
        int s = g_csrc[e];
        float4 v = *reinterpret_cast<const float4*>(&y[s * 128 + lane * 4]);
        a.x += v.x; a.y += v.y; a.z += v.z; a.w += v.w;
    }

    float4 self = *reinterpret_cast<const float4*>(&y[node * 128 + lane * 4]);
    float  di   = g_dinv[node];
    int    c    = lane * 4;
    float4 bv   = *reinterpret_cast<const float4*>(&bias[c]);
    float4 o;
    o.x = fmaxf(di * (a.x + self.x) + bv.x, 0.f);
    o.y = fmaxf(di * (a.y + self.y) + bv.y, 0.f);
    o.z = fmaxf(di * (a.z + self.z) + bv.z, 0.f);
    o.w = fmaxf(di * (a.w + self.w) + bv.w, 0.f);

    if (MODE == 0) {
        *reinterpret_cast<float4*>(&h[node * 128 + c]) = o;
    } else {
        float4 gm = *reinterpret_cast<const float4*>(&gamma[c]);
        float4 bt = *reinterpret_cast<const float4*>(&beta[c]);
        float4 mu = *reinterpret_cast<const float4*>(&rmean[c]);
        float4 va = *reinterpret_cast<const float4*>(&rvar[c]);
        float4 v;
        v.x = (o.x - mu.x) * rsqrtf(va.x + BN_EPS) * gm.x + bt.x;
        v.y = (o.y - mu.y) * rsqrtf(va.y + BN_EPS) * gm.y + bt.y;
        v.z = (o.z - mu.z) * rsqrtf(va.z + BN_EPS) * gm.z + bt.z;
        v.w = (o.w - mu.w) * rsqrtf(va.w + BN_EPS) * gm.w + bt.w;
        unsigned* p = &g_gmax[batch[node] * 128 + c];
        atomicMax(p + 0, enc_f(v.x));
        atomicMax(p + 1, enc_f(v.y));
        atomicMax(p + 2, enc_f(v.z));
        atomicMax(p + 3, enc_f(v.w));
    }
}

__global__ void decode_g() {
    int i = blockIdx.x * blockDim.x + threadIdx.x;
    if (i < NG * NF) g_g[i] = dec_f(g_gmax[i]);
}

// ---------------- small GEMM (one block per row) ---------------------------
__global__ void small_gemm(const float* __restrict__ A, const float* __restrict__ W,
                           const float* __restrict__ b, float* __restrict__ out,
                           int K, int ncols, int do_relu)
{
    __shared__ float xs[128];
    int row = blockIdx.x;
    for (int k = threadIdx.x; k < K; k += blockDim.x) xs[k] = A[row * K + k];
    __syncthreads();
    int c = threadIdx.x;
    if (c < ncols) {
        float s = b[c];
        for (int k = 0; k < K; ++k) s += xs[k] * W[k * ncols + c];
        out[row * ncols + c] = do_relu ? fmaxf(s, 0.f) : s;
    }
}

// ---------------- launch ---------------------------------------------------
extern "C" void kernel_launch(void* const* d_in, const int* in_sizes, int n_in,
                              void* d_out, int out_size)
{
    const float* x     = (const float*)d_in[0];
    const int*   ei    = (const int*)  d_in[1];
    const int*   batch = (const int*)  d_in[2];
    const float* W1 = (const float*)d_in[3];  const float* b1 = (const float*)d_in[4];
    const float* W2 = (const float*)d_in[5];  const float* b2 = (const float*)d_in[6];
    const float* W3 = (const float*)d_in[7];  const float* b3 = (const float*)d_in[8];
    const float* gamma = (const float*)d_in[9];
    const float* beta  = (const float*)d_in[10];
    const float* rmean = (const float*)d_in[11];
    const float* rvar  = (const float*)d_in[12];
    const float* lw1 = (const float*)d_in[13]; const float* lb1 = (const float*)d_in[14];
    const float* lw2 = (const float*)d_in[15]; const float* lb2 = (const float*)d_in[16];
    const float* lw3 = (const float*)d_in[17]; const float* lb3 = (const float*)d_in[18];
    float* out = (float*)d_out;

    const int* src = ei;
    const int* dst = ei + N_EDGES;

    void *p_deg, *p_dinv, *p_y, *p_h, *p_gmax, *p_g, *p_m1, *p_m2;
    cudaGetSymbolAddress(&p_deg,  g_deg);
    cudaGetSymbolAddress(&p_dinv, g_dinv);
    cudaGetSymbolAddress(&p_y,    g_y);
    cudaGetSymbolAddress(&p_h,    g_h);
    cudaGetSymbolAddress(&p_gmax, g_gmax);
    cudaGetSymbolAddress(&p_g,    g_g);
    cudaGetSymbolAddress(&p_m1,   g_m1);
    cudaGetSymbolAddress(&p_m2,   g_m2);
    float* y = (float*)p_y;
    float* h = (float*)p_h;
    const float* dinv = (const float*)p_dinv;

    const int EB = (N_EDGES + 255) / 256;
    const int NB = (N_NODES + 255) / 256;
    const int GRID_GEMM = (N_NODES + 127) / 128;
    const int GRID_AGG  = (N_NODES + 7) / 8;

    // CSR build + dinv
    zero_i<<<NB, 256>>>((int*)p_deg, N_NODES);
    deg_count<<<EB, 256>>>(dst);
    scan_deg<<<1, 1024>>>();
    csr_fill<<<EB, 256>>>(src, dst);
    zero_u<<<(NG * NF + 255) / 256, 256>>>((unsigned*)p_gmax, NG * NF);

    // layer 1
    gemm_f32x2<<<GRID_GEMM, 256>>>(x, W1, y, dinv, nullptr, N_NODES, 0);
    aggregate<0><<<GRID_AGG, 256>>>(y, b1, h, nullptr, nullptr, nullptr, nullptr, nullptr);
    // layer 2
    gemm_f32x2<<<GRID_GEMM, 256>>>(h, W2, y, dinv, nullptr, N_NODES, 0);
    aggregate<0><<<GRID_AGG, 256>>>(y, b2, h, nullptr, nullptr, nullptr, nullptr, nullptr);
    // layer 3 + BN + pool
    gemm_f32x2<<<GRID_GEMM, 256>>>(h, W3, y, dinv, nullptr, N_NODES, 0);
    aggregate<1><<<GRID_AGG, 256>>>(y, b3, nullptr, batch, gamma, beta, rmean, rvar);

    decode_g<<<(NG * NF + 255) / 256, 256>>>();

    // MLP head
    gemm_f32x2<<<(NG + 127) / 128, 256>>>((const float*)p_g, lw1, (float*)p_m1,
                                          nullptr, lb1, NG, 1);
    small_gemm<<<NG, 64>>>((const float*)p_m1, lw2, lb2, (float*)p_m2, 128, 64, 1);
    small_gemm<<<NG, 64>>>((const float*)p_m2, lw3, lb3, out, 64, NC, 0);
}

// round 5
// speedup vs baseline: 1.4778x; 1.4778x over previous
#include <cuda_runtime.h>
#include <cuda_bf16.h>
#include <math.h>
#include <stdint.h>

#define N_NODES 50000
#define N_EDGES 600000
#define NF      128
#define NG      512
#define NC      10
#define BN_EPS  1e-5f

// ---------------- scratch (device globals) ---------------------------------
__device__ int      g_deg   [N_NODES];
__device__ int      g_rowptr[N_NODES + 1];
__device__ int      g_cursor[N_NODES];
__device__ int      g_csrc  [N_EDGES];
__device__ float    g_dinv  [N_NODES];
__device__ float    g_y     [N_NODES * NF];
__device__ float    g_h     [N_NODES * NF];
__device__ unsigned g_gmax  [NG * NF];
__device__ float    g_g     [NG * NF];
__device__ float    g_m1    [NG * NF];
__device__ float    g_m2    [NG * 64];
// B fragments for mma.sync m16n8k16, pre-laid-out in register order:
// [L(4)][kc(4)][s(2)][nt(16)][hl(2)][lane(32)][j(2)] as uint32 (bf16x2)
__device__ unsigned g_bfrag[4 * 4 * 2 * 16 * 2 * 32 * 2];

// ---------------- helpers --------------------------------------------------
__device__ __forceinline__ unsigned enc_f(float v) {
    unsigned u = __float_as_uint(v);
    return (u & 0x80000000u) ? ~u : (u | 0x80000000u);
}
__device__ __forceinline__ float dec_f(unsigned u) {
    return (u & 0x80000000u) ? __uint_as_float(u & 0x7FFFFFFFu)
                             : __uint_as_float(~u);
}

// ---------------- CSR build -------------------------------------------------
__global__ void zero_i(int* p, int n) {
    int i = blockIdx.x * blockDim.x + threadIdx.x;
    if (i < n) p[i] = 0;
}
__global__ void zero_u(unsigned* p, int n) {
    int i = blockIdx.x * blockDim.x + threadIdx.x;
    if (i < n) p[i] = 0u;
}
__global__ void deg_count(const int* __restrict__ dst) {
    int e = blockIdx.x * blockDim.x + threadIdx.x;
    if (e < N_EDGES) atomicAdd(&g_deg[dst[e]], 1);
}
__global__ __launch_bounds__(1024) void scan_deg() {
    __shared__ int sums[1024];
    const int CH = (N_NODES + 1023) / 1024;
    int t = threadIdx.x;
    int base = t * CH;
    int s = 0;
    for (int i = 0; i < CH; ++i) {
        int idx = base + i;
        if (idx < N_NODES) s += g_deg[idx];
    }
    sums[t] = s;
    __syncthreads();
    for (int off = 1; off < 1024; off <<= 1) {
        int v = 0;
        if (t >= off) v = sums[t - off];
        __syncthreads();
        if (t >= off) sums[t] += v;
        __syncthreads();
    }
    int run = (t == 0) ? 0 : sums[t - 1];
    for (int i = 0; i < CH; ++i) {
        int idx = base + i;
        if (idx < N_NODES) {
            g_rowptr[idx] = run;
            g_cursor[idx] = run;
            g_dinv[idx]   = rsqrtf((float)g_deg[idx] + 1.0f);
            run += g_deg[idx];
        }
    }
    if (t == 1023) g_rowptr[N_NODES] = run;
}
__global__ void csr_fill(const int* __restrict__ src, const int* __restrict__ dst) {
    int e = blockIdx.x * blockDim.x + threadIdx.x;
    if (e < N_EDGES) {
        int pos = atomicAdd(&g_cursor[dst[e]], 1);
        g_csrc[pos] = src[e];
    }
}

// ---------------- W pre-convert into mma B-fragment layout ------------------
// B frag (col-major k x n, m16n8k16): lane l holds
//   b0 = {B[k0+(l%4)*2][n0+l/4], B[k0+(l%4)*2+1][..]}   (j=0)
//   b1 = {B[k0+8+(l%4)*2][..],   B[k0+9+(l%4)*2][..]}   (j=1)
__global__ void prep_w(const float* __restrict__ W1, const float* __restrict__ W2,
                       const float* __restrict__ W3, const float* __restrict__ LW1) {
    int i = blockIdx.x * blockDim.x + threadIdx.x;
    if (i >= 4 * NF * NF) return;
    int L = i >> 14;
    int r = i & 16383;
    int k = r >> 7;
    int n = r & 127;
    const float* W = (L == 0) ? W1 : (L == 1) ? W2 : (L == 2) ? W3 : LW1;
    float v = W[k * NF + n];
    __nv_bfloat16 hi = __float2bfloat16(v);
    __nv_bfloat16 lo = __float2bfloat16(v - __bfloat162float(hi));
    int kc = k >> 5;
    int s  = (k >> 4) & 1;
    int ko = k & 15;
    int nt = n >> 3;
    int lane = (n & 7) * 4 + ((ko & 7) >> 1);
    int j    = ko >> 3;
    int half = ko & 1;
    unsigned short* p = reinterpret_cast<unsigned short*>(g_bfrag);
    size_t bh = (((((size_t)((L * 4 + kc) * 2 + s) * 16 + nt) * 2 + 0) * 32 + lane) * 2 + j) * 2 + half;
    size_t bl = (((((size_t)((L * 4 + kc) * 2 + s) * 16 + nt) * 2 + 1) * 32 + lane) * 2 + j) * 2 + half;
    p[bh] = __bfloat16_as_ushort(hi);
    p[bl] = __bfloat16_as_ushort(lo);
}

// ---------------- mma.sync GEMM: out = (A @ W_L) * dinv  [+bias][relu] ------
// 128x128 CTA tile, 8 warps x (32 rows x 64 cols), K chunks of 32,
// bf16 hi/lo 3-pass split, fp32 accumulate.
#define ASTRIDE 20   // uint32 per row (bank-conflict-free fragment fetch)

__device__ __forceinline__ void mma_bf16(float* d, const unsigned* a, unsigned b0, unsigned b1) {
    asm volatile(
        "mma.sync.aligned.m16n8k16.row.col.f32.bf16.bf16.f32 "
        "{%0,%1,%2,%3}, {%4,%5,%6,%7}, {%8,%9}, {%0,%1,%2,%3};"
        : "+f"(d[0]), "+f"(d[1]), "+f"(d[2]), "+f"(d[3])
        : "r"(a[0]), "r"(a[1]), "r"(a[2]), "r"(a[3]), "r"(b0), "r"(b1));
}

__global__ __launch_bounds__(256)
void gemm_mma(const float* __restrict__ A, int L, float* __restrict__ out,
              const float* __restrict__ dinv, const float* __restrict__ bias,
              int nrows, int do_relu)
{
    __shared__ unsigned AshH[128 * ASTRIDE];
    __shared__ unsigned AshL[128 * ASTRIDE];

    const int tid   = threadIdx.x;
    const int warp  = tid >> 5;
    const int lane  = tid & 31;
    const int l4    = lane >> 2;      // 0..7
    const int lm    = lane & 3;       // 0..3
    const int mrowg = (warp & 3) * 32;
    const int ncolg = (warp >> 2) * 64;
    const int row0  = blockIdx.x * 128;

    float d[2][8][4];
    #pragma unroll
    for (int mt = 0; mt < 2; ++mt)
        #pragma unroll
        for (int nt = 0; nt < 8; ++nt)
            #pragma unroll
            for (int q = 0; q < 4; ++q) d[mt][nt][q] = 0.f;

    const int arow  = tid >> 1;       // 0..127
    const int ahalf = tid & 1;        // cols ahalf*16..+15

    for (int kc = 0; kc < 4; ++kc) {
        // ---- load + convert A chunk: rows 0..127, k = kc*32 + [0..31] ----
        {
            int gr = row0 + arow;
            #pragma unroll
            for (int q = 0; q < 4; ++q) {
                float4 v = make_float4(0.f, 0.f, 0.f, 0.f);
                if (gr < nrows)
                    v = *reinterpret_cast<const float4*>(
                        &A[gr * NF + kc * 32 + ahalf * 16 + q * 4]);
                __nv_bfloat16 hx = __float2bfloat16(v.x);
                __nv_bfloat16 hy = __float2bfloat16(v.y);
                __nv_bfloat16 hz = __float2bfloat16(v.z);
                __nv_bfloat16 hw = __float2bfloat16(v.w);
                unsigned hp0 = ((unsigned)__bfloat16_as_ushort(hy) << 16) | __bfloat16_as_ushort(hx);
                unsigned hp1 = ((unsigned)__bfloat16_as_ushort(hw) << 16) | __bfloat16_as_ushort(hz);
                __nv_bfloat16 lx = __float2bfloat16(v.x - __bfloat162float(hx));
                __nv_bfloat16 ly = __float2bfloat16(v.y - __bfloat162float(hy));
                __nv_bfloat16 lz = __float2bfloat16(v.z - __bfloat162float(hz));
                __nv_bfloat16 lw = __float2bfloat16(v.w - __bfloat162float(hw));
                unsigned lp0 = ((unsigned)__bfloat16_as_ushort(ly) << 16) | __bfloat16_as_ushort(lx);
                unsigned lp1 = ((unsigned)__bfloat16_as_ushort(lw) << 16) | __bfloat16_as_ushort(lz);
                int p = ahalf * 8 + q * 2;
                AshH[arow * ASTRIDE + p + 0] = hp0;
                AshH[arow * ASTRIDE + p + 1] = hp1;
                AshL[arow * ASTRIDE + p + 0] = lp0;
                AshL[arow * ASTRIDE + p + 1] = lp1;
            }
        }
        __syncthreads();

        #pragma unroll
        for (int s = 0; s < 2; ++s) {
            // ---- A fragments (hi and lo) for 2 m-tiles ----
            unsigned aH[2][4], aL[2][4];
            #pragma unroll
            for (int mt = 0; mt < 2; ++mt) {
                int rbase = mrowg + mt * 16;
                int p0 = s * 8 + lm;
                aH[mt][0] = AshH[(rbase + l4)     * ASTRIDE + p0];
                aH[mt][1] = AshH[(rbase + l4 + 8) * ASTRIDE + p0];
                aH[mt][2] = AshH[(rbase + l4)     * ASTRIDE + p0 + 4];
                aH[mt][3] = AshH[(rbase + l4 + 8) * ASTRIDE + p0 + 4];
                aL[mt][0] = AshL[(rbase + l4)     * ASTRIDE + p0];
                aL[mt][1] = AshL[(rbase + l4 + 8) * ASTRIDE + p0];
                aL[mt][2] = AshL[(rbase + l4)     * ASTRIDE + p0 + 4];
                aL[mt][3] = AshL[(rbase + l4 + 8) * ASTRIDE + p0 + 4];
            }
            // ---- B fragments + mma ----
            #pragma unroll
            for (int nt = 0; nt < 8; ++nt) {
                int ntg = (ncolg >> 3) + nt;
                size_t idx = (((size_t)((L * 4 + kc) * 2 + s) * 16 + ntg) * 2) * 64 + lane * 2;
                uint2 bH = *reinterpret_cast<const uint2*>(&g_bfrag[idx]);
                uint2 bL = *reinterpret_cast<const uint2*>(&g_bfrag[idx + 64]);
                #pragma unroll
                for (int mt = 0; mt < 2; ++mt) {
                    mma_bf16(d[mt][nt], aH[mt], bH.x, bH.y);
                    mma_bf16(d[mt][nt], aH[mt], bL.x, bL.y);
                    mma_bf16(d[mt][nt], aL[mt], bH.x, bH.y);
                }
            }
        }
        __syncthreads();
    }

    // ---- epilogue: d-frag rows l4 / l4+8, cols (lm*2, +1) ----
    #pragma unroll
    for (int mt = 0; mt < 2; ++mt) {
        int r_lo = row0 + mrowg + mt * 16 + l4;
        int r_hi = r_lo + 8;
        float s_lo = 1.f, s_hi = 1.f;
        if (dinv) {
            if (r_lo < nrows) s_lo = dinv[r_lo];
            if (r_hi < nrows) s_hi = dinv[r_hi];
        }
        #pragma unroll
        for (int nt = 0; nt < 8; ++nt) {
            int col = ncolg + nt * 8 + lm * 2;
            float b0 = 0.f, b1 = 0.f;
            if (bias) { b0 = bias[col]; b1 = bias[col + 1]; }
            float2 v0 = make_float2(d[mt][nt][0] * s_lo + b0, d[mt][nt][1] * s_lo + b1);
            float2 v1 = make_float2(d[mt][nt][2] * s_hi + b0, d[mt][nt][3] * s_hi + b1);
            if (do_relu) {
                v0.x = fmaxf(v0.x, 0.f); v0.y = fmaxf(v0.y, 0.f);
                v1.x = fmaxf(v1.x, 0.f); v1.y = fmaxf(v1.y, 0.f);
            }
            if (r_lo < nrows)
                *reinterpret_cast<float2*>(&out[r_lo * NF + col]) = v0;
            if (r_hi < nrows)
                *reinterpret_cast<float2*>(&out[r_hi * NF + col]) = v1;
        }
    }
}

// ---------------- aggregate (CSR gather) + fused epilogue ------------------
template <int MODE>
__global__ __launch_bounds__(256)
void aggregate(const float* __restrict__ y, const float* __restrict__ bias,
               float* __restrict__ h,
               const int* __restrict__ batch,
               const float* __restrict__ gamma, const float* __restrict__ beta,
               const float* __restrict__ rmean, const float* __restrict__ rvar)
{
    int node = blockIdx.x * 8 + (threadIdx.x >> 5);
    int lane = threadIdx.x & 31;
    if (node >= N_NODES) return;

    int p0 = g_rowptr[node];
    int p1 = g_rowptr[node + 1];

    float4 a = make_float4(0.f, 0.f, 0.f, 0.f);
    int e = p0;
    for (; e + 4 <= p1; e += 4) {
        int s0 = g_csrc[e + 0];
        int s1 = g_csrc[e + 1];
        int s2 = g_csrc[e + 2];
        int s3 = g_csrc[e + 3];
        float4 v0 = *reinterpret_cast<const float4*>(&y[s0 * 128 + lane * 4]);
        float4 v1 = *reinterpret_cast<const float4*>(&y[s1 * 128 + lane * 4]);
        float4 v2 = *reinterpret_cast<const float4*>(&y[s2 * 128 + lane * 4]);
        float4 v3 = *reinterpret_cast<const float4*>(&y[s3 * 128 + lane * 4]);
        a.x += (v0.x + v1.x) + (v2.x + v3.x);
        a.y += (v0.y + v1.y) + (v2.y + v3.y);
        a.z += (v0.z + v1.z) + (v2.z + v3.z);
        a.w += (v0.w + v1.w) + (v2.w + v3.w);
    }
    for (; e < p1; ++e) {
        int s = g_csrc[e];
        float4 v = *reinterpret_cast<const float4*>(&y[s * 128 + lane * 4]);
        a.x += v.x; a.y += v.y; a.z += v.z; a.w += v.w;
    }

    float4 self = *reinterpret_cast<const float4*>(&y[node * 128 + lane * 4]);
    float  di   = g_dinv[node];
    int    c    = lane * 4;
    float4 bv   = *reinterpret_cast<const float4*>(&bias[c]);
    float4 o;
    o.x = fmaxf(di * (a.x + self.x) + bv.x, 0.f);
    o.y = fmaxf(di * (a.y + self.y) + bv.y, 0.f);
    o.z = fmaxf(di * (a.z + self.z) + bv.z, 0.f);
    o.w = fmaxf(di * (a.w + self.w) + bv.w, 0.f);

    if (MODE == 0) {
        *reinterpret_cast<float4*>(&h[node * 128 + c]) = o;
    } else {
        float4 gm = *reinterpret_cast<const float4*>(&gamma[c]);
        float4 bt = *reinterpret_cast<const float4*>(&beta[c]);
        float4 mu = *reinterpret_cast<const float4*>(&rmean[c]);
        float4 va = *reinterpret_cast<const float4*>(&rvar[c]);
        float4 v;
        v.x = (o.x - mu.x) * rsqrtf(va.x + BN_EPS) * gm.x + bt.x;
        v.y = (o.y - mu.y) * rsqrtf(va.y + BN_EPS) * gm.y + bt.y;
        v.z = (o.z - mu.z) * rsqrtf(va.z + BN_EPS) * gm.z + bt.z;
        v.w = (o.w - mu.w) * rsqrtf(va.w + BN_EPS) * gm.w + bt.w;
        unsigned* p = &g_gmax[batch[node] * 128 + c];
        atomicMax(p + 0, enc_f(v.x));
        atomicMax(p + 1, enc_f(v.y));
        atomicMax(p + 2, enc_f(v.z));
        atomicMax(p + 3, enc_f(v.w));
    }
}

__global__ void decode_g() {
    int i = blockIdx.x * blockDim.x + threadIdx.x;
    if (i < NG * NF) g_g[i] = dec_f(g_gmax[i]);
}

// ---------------- small GEMM (one block per row) ---------------------------
__global__ void small_gemm(const float* __restrict__ A, const float* __restrict__ W,
                           const float* __restrict__ b, float* __restrict__ out,
                           int K, int ncols, int do_relu)
{
    __shared__ float xs[128];
    int row = blockIdx.x;
    for (int k = threadIdx.x; k < K; k += blockDim.x) xs[k] = A[row * K + k];
    __syncthreads();
    int c = threadIdx.x;
    if (c < ncols) {
        float s = b[c];
        for (int k = 0; k < K; ++k) s += xs[k] * W[k * ncols + c];
        out[row * ncols + c] = do_relu ? fmaxf(s, 0.f) : s;
    }
}

// ---------------- launch ---------------------------------------------------
extern "C" void kernel_launch(void* const* d_in, const int* in_sizes, int n_in,
                              void* d_out, int out_size)
{
    const float* x     = (const float*)d_in[0];
    const int*   ei    = (const int*)  d_in[1];
    const int*   batch = (const int*)  d_in[2];
    const float* W1 = (const float*)d_in[3];  const float* b1 = (const float*)d_in[4];
    const float* W2 = (const float*)d_in[5];  const float* b2 = (const float*)d_in[6];
    const float* W3 = (const float*)d_in[7];  const float* b3 = (const float*)d_in[8];
    const float* gamma = (const float*)d_in[9];
    const float* beta  = (const float*)d_in[10];
    const float* rmean = (const float*)d_in[11];
    const float* rvar  = (const float*)d_in[12];
    const float* lw1 = (const float*)d_in[13]; const float* lb1 = (const float*)d_in[14];
    const float* lw2 = (const float*)d_in[15]; const float* lb2 = (const float*)d_in[16];
    const float* lw3 = (const float*)d_in[17]; const float* lb3 = (const float*)d_in[18];
    float* out = (float*)d_out;

    const int* src = ei;
    const int* dst = ei + N_EDGES;

    void *p_deg, *p_dinv, *p_y, *p_h, *p_gmax, *p_g, *p_m1, *p_m2;
    cudaGetSymbolAddress(&p_deg,  g_deg);
    cudaGetSymbolAddress(&p_dinv, g_dinv);
    cudaGetSymbolAddress(&p_y,    g_y);
    cudaGetSymbolAddress(&p_h,    g_h);
    cudaGetSymbolAddress(&p_gmax, g_gmax);
    cudaGetSymbolAddress(&p_g,    g_g);
    cudaGetSymbolAddress(&p_m1,   g_m1);
    cudaGetSymbolAddress(&p_m2,   g_m2);
    float* y = (float*)p_y;
    float* h = (float*)p_h;
    const float* dinv = (const float*)p_dinv;

    const int EB = (N_EDGES + 255) / 256;
    const int NB = (N_NODES + 255) / 256;
    const int GRID_GEMM = (N_NODES + 127) / 128;
    const int GRID_AGG  = (N_NODES + 7) / 8;

    // CSR build + dinv + weight fragment prep
    zero_i<<<NB, 256>>>((int*)p_deg, N_NODES);
    deg_count<<<EB, 256>>>(dst);
    scan_deg<<<1, 1024>>>();
    csr_fill<<<EB, 256>>>(src, dst);
    prep_w<<<(4 * NF * NF + 255) / 256, 256>>>(W1, W2, W3, lw1);
    zero_u<<<(NG * NF + 255) / 256, 256>>>((unsigned*)p_gmax, NG * NF);

    // layer 1
    gemm_mma<<<GRID_GEMM, 256>>>(x, 0, y, dinv, nullptr, N_NODES, 0);
    aggregate<0><<<GRID_AGG, 256>>>(y, b1, h, nullptr, nullptr, nullptr, nullptr, nullptr);
    // layer 2
    gemm_mma<<<GRID_GEMM, 256>>>(h, 1, y, dinv, nullptr, N_NODES, 0);
    aggregate<0><<<GRID_AGG, 256>>>(y, b2, h, nullptr, nullptr, nullptr, nullptr, nullptr);
    // layer 3 + BN + pool
    gemm_mma<<<GRID_GEMM, 256>>>(h, 2, y, dinv, nullptr, N_NODES, 0);
    aggregate<1><<<GRID_AGG, 256>>>(y, b3, nullptr, batch, gamma, beta, rmean, rvar);

    decode_g<<<(NG * NF + 255) / 256, 256>>>();

    // MLP head
    gemm_mma<<<(NG + 127) / 128, 256>>>((const float*)p_g, 3, (float*)p_m1,
                                        nullptr, lb1, NG, 1);
    small_gemm<<<NG, 64>>>((const float*)p_m1, lw2, lb2, (float*)p_m2, 128, 64, 1);
    small_gemm<<<NG, 64>>>((const float*)p_m2, lw3, lb3, out, 64, NC, 0);
}